// round 8
// baseline (speedup 1.0000x reference)
#include <cuda_runtime.h>
#include <cstdint>

#define Bsz 64
#define Ssz 2048
#define Isz 512
#define Hsz 512

// ============================================================
// Phase 1: xW = x @ W + b   (M=131072, K=512, N=512)
// 128x128 block tile, BK=8, 256 threads, 8x8 thread tile,
// packed f32x2 FMA. 2 CTAs/SM hides sync bubbles.
// ============================================================
__global__ __launch_bounds__(256, 2) void sgemm_xw(
    const float* __restrict__ A,
    const float* __restrict__ Wm,
    const float* __restrict__ bias,
    float* __restrict__ C)
{
    constexpr int K = 512, N = 512;
    __shared__ float As[8][128];
    __shared__ float Bs[8][128];

    const int tid  = threadIdx.x;
    const int bm   = blockIdx.y, bn = blockIdx.x;
    const int arow = tid >> 1, acol = (tid & 1) << 2;
    const int brow = tid >> 5, bcol = (tid & 31) << 2;
    const int tx   = tid & 15, ty = tid >> 4;

    const float* Ab = A + (size_t)bm * 128 * K;
    const float* Bb = Wm + bn * 128;

    unsigned long long acc[8][4];
#pragma unroll
    for (int i = 0; i < 8; i++)
#pragma unroll
        for (int j = 0; j < 4; j++) acc[i][j] = 0ull;

    for (int kk = 0; kk < K; kk += 8) {
        float4 av = *(const float4*)(Ab + (size_t)arow * K + kk + acol);
        float4 bv = *(const float4*)(Bb + (size_t)(kk + brow) * N + bcol);
        __syncthreads();
        As[acol + 0][arow] = av.x;
        As[acol + 1][arow] = av.y;
        As[acol + 2][arow] = av.z;
        As[acol + 3][arow] = av.w;
        *(float4*)&Bs[brow][bcol] = bv;
        __syncthreads();
#pragma unroll
        for (int k = 0; k < 8; k++) {
            float4 a0 = *(const float4*)&As[k][ty * 8];
            float4 a1 = *(const float4*)&As[k][ty * 8 + 4];
            ulonglong2 b0 = *(const ulonglong2*)&Bs[k][tx * 8];
            ulonglong2 b1 = *(const ulonglong2*)&Bs[k][tx * 8 + 4];
            float ar[8] = {a0.x, a0.y, a0.z, a0.w, a1.x, a1.y, a1.z, a1.w};
            unsigned long long br[4] = {b0.x, b0.y, b1.x, b1.y};
#pragma unroll
            for (int i = 0; i < 8; i++) {
                unsigned long long ad;
                unsigned int au = __float_as_uint(ar[i]);
                asm("mov.b64 %0, {%1, %1};" : "=l"(ad) : "r"(au));
#pragma unroll
                for (int j = 0; j < 4; j++)
                    asm("fma.rn.f32x2 %0, %1, %2, %0;"
                        : "+l"(acc[i][j]) : "l"(ad), "l"(br[j]));
            }
        }
    }

    const int cb = bn * 128 + tx * 8;
    ulonglong2 bb0 = *(const ulonglong2*)&bias[cb];
    ulonglong2 bb1 = *(const ulonglong2*)&bias[cb + 4];
    unsigned long long bz[4] = {bb0.x, bb0.y, bb1.x, bb1.y};
#pragma unroll
    for (int i = 0; i < 8; i++) {
        size_t row = (size_t)bm * 128 + ty * 8 + i;
        float* Crow = C + row * N + cb;
#pragma unroll
        for (int j = 0; j < 4; j++) {
            unsigned long long v;
            asm("add.rn.f32x2 %0, %1, %2;" : "=l"(v) : "l"(acc[i][j]), "l"(bz[j]));
            *(unsigned long long*)(Crow + 2 * j) = v;
        }
    }
}

// fast tanh: 1 - 2/(exp(2x)+1) via MUFU EX2 + RCP (abs err ~1e-7).
__device__ __forceinline__ float fast_tanh(float x) {
    float e;
    asm("ex2.approx.f32 %0, %1;" : "=f"(e) : "f"(x * 2.8853900817779268f));
    float r;
    asm("rcp.approx.f32 %0, %1;" : "=f"(r) : "f"(e + 1.0f));
    return fmaf(-2.0f, r, 1.0f);
}

__device__ __forceinline__ void mbar_wait(unsigned int addr, unsigned int parity) {
    unsigned int done;
    do {
        asm volatile(
            "{\n\t.reg .pred p;\n\t"
            "mbarrier.try_wait.parity.acquire.cta.shared::cta.b64 p, [%1], %2, 0x989680;\n\t"
            "selp.b32 %0, 1, 0, p;\n\t}"
            : "=r"(done) : "r"(addr), "r"(parity) : "memory");
    } while (!done);
}

// ============================================================
// Phase 2: persistent cluster RNN scan (st.async exchange).
// 16 clusters x 8 CTAs, 256 threads/CTA. Cluster owns 4 batches;
// CTA rank r owns U columns [64r,64r+64) as pre-packed k-pairs in
// registers. Per step:
//   wait(mb[q]) -> FMA partials -> red -> sync ->
//   256-thread epilogue: tanh, then 7x st.async.b32 fire the value
//   straight to the peers' hbuf[q^1]+mbarrier (complete_tx), plus
//   local store + hidden STG -> sync.
// No bulk-copy engine, no fence, no staging barrier for sends.
// ============================================================
__global__ void __launch_bounds__(256, 1) __cluster_dims__(8, 1, 1)
rnn_scan(const float* __restrict__ U,      // [512,512] row-major [k][h]
         float* __restrict__ hidden,       // [B,S,H]: in = xW+b, out = h
         float* __restrict__ hlast)        // [B,H]
{
    __shared__ __align__(128) float hbuf[2][256][4][2];  // [buf][kp][b][kk] 16KB
    __shared__ __align__(16)  float red[4][64][4];       // [ks][col][b]
    __shared__ __align__(16)  unsigned long long mbar[2];

    const int tid = threadIdx.x;
    unsigned int rank;
    asm("mov.u32 %0, %%cluster_ctarank;" : "=r"(rank));
    const int cid = blockIdx.x >> 3;
    const int b0  = cid * 4;
    const int ks  = tid >> 6;              // 0..3 (k-pair split)
    const int c   = tid & 63;
    const int cg  = (int)rank * 64 + c;

    // Pre-pack U k-pairs: Upack[j] = (U[k0][cg], U[k0+1][cg]), k0 = ks*128+2j.
    unsigned long long Upack[64];
#pragma unroll
    for (int j = 0; j < 64; j++) {
        int k0 = ks * 128 + 2 * j;
        unsigned int lo = __float_as_uint(U[(size_t)k0 * Hsz + cg]);
        unsigned int hi = __float_as_uint(U[(size_t)(k0 + 1) * Hsz + cg]);
        asm("mov.b64 %0, {%1, %2};" : "=l"(Upack[j]) : "r"(lo), "r"(hi));
    }

    const unsigned int hb_base =
        (unsigned int)__cvta_generic_to_shared(&hbuf[0][0][0][0]);
    const unsigned int mb_base =
        (unsigned int)__cvta_generic_to_shared(&mbar[0]);

    // Epilogue mapping: all 256 threads, one (col, batch) value each.
    // eb = warp-pair id -> batch, ec -> column (coalesced STG).
    const int ec  = tid & 63;
    const int eb  = tid >> 6;
    const int egc = (int)rank * 64 + ec;

    // Hoisted DSMEM targets: this thread's h-slot and mbarrier in each peer
    // (buffer 0 addresses; buffer 1 = +8192 / +8).
    const unsigned int lslot =
        hb_base + (unsigned int)((egc >> 1) * 32 + eb * 8 + (egc & 1) * 4);
    unsigned int ra[7], rm[7];
#pragma unroll
    for (int r = 0; r < 7; r++) {
        const unsigned int pr = (rank + 1u + (unsigned int)r) & 7u;
        asm("mapa.shared::cluster.u32 %0, %1, %2;"
            : "=r"(ra[r]) : "r"(lslot), "r"(pr));
        asm("mapa.shared::cluster.u32 %0, %1, %2;"
            : "=r"(rm[r]) : "r"(mb_base), "r"(pr));
    }

    // Init: zero both h buffers; mbarriers count=1; pre-arm mb[1].
    {
        float* hz = &hbuf[0][0][0][0];
        for (int i = tid; i < 2 * 256 * 4 * 2; i += 256) hz[i] = 0.0f;
    }
    if (tid == 0) {
        asm volatile("mbarrier.init.shared.b64 [%0], %1;"
                     :: "r"(mb_base), "r"(1u) : "memory");
        asm volatile("mbarrier.init.shared.b64 [%0], %1;"
                     :: "r"(mb_base + 8), "r"(1u) : "memory");
        asm volatile("mbarrier.arrive.expect_tx.shared.b64 _, [%0], %1;"
                     :: "r"(mb_base + 8), "r"(7168u) : "memory");
    }
    __syncthreads();
    asm volatile("barrier.cluster.arrive.aligned;" ::: "memory");
    asm volatile("barrier.cluster.wait.aligned;" ::: "memory");

    size_t gaddr = ((size_t)(b0 + eb) * Ssz) * Hsz + egc;
    unsigned int ph0 = 0, ph1 = 0;

    for (int t = 0; t < Ssz; t++) {
        const int q = t & 1;
        const unsigned int mbq = mb_base + (unsigned int)q * 8;

        // xw prefetch (independent of the wait; issue early).
        const float xw = __ldg(hidden + gaddr);

        // Wait for this step's h (buffer q), except t=0 (zeros).
        if (t > 0) {
            if (q == 0) { mbar_wait(mbq, ph0); ph0 ^= 1; }
            else        { mbar_wait(mbq, ph1); ph1 ^= 1; }
        }
        // Re-arm mb[q] for its next phase (consumed at t+2).
        if (tid == 0)
            asm volatile("mbarrier.arrive.expect_tx.shared.b64 _, [%0], %1;"
                         :: "r"(mbq), "r"(7168u) : "memory");

        // ---- partials: 4 batches x 1 col x 64 k-pairs (f32x2) ----
        const ulonglong2* hk = (const ulonglong2*)&hbuf[q][ks * 64][0][0];
        unsigned long long a0 = 0ull, a1 = 0ull, a2 = 0ull, a3 = 0ull;
#pragma unroll
        for (int j = 0; j < 64; j++) {
            ulonglong2 p01 = hk[2 * j];       // b0, b1 pairs
            ulonglong2 p23 = hk[2 * j + 1];   // b2, b3 pairs
            asm("fma.rn.f32x2 %0, %1, %2, %0;" : "+l"(a0) : "l"(Upack[j]), "l"(p01.x));
            asm("fma.rn.f32x2 %0, %1, %2, %0;" : "+l"(a1) : "l"(Upack[j]), "l"(p01.y));
            asm("fma.rn.f32x2 %0, %1, %2, %0;" : "+l"(a2) : "l"(Upack[j]), "l"(p23.x));
            asm("fma.rn.f32x2 %0, %1, %2, %0;" : "+l"(a3) : "l"(Upack[j]), "l"(p23.y));
        }
        float s0, s1, s2, s3;
        {
            unsigned int l, h;
            asm("mov.b64 {%0, %1}, %2;" : "=r"(l), "=r"(h) : "l"(a0));
            s0 = __uint_as_float(l) + __uint_as_float(h);
            asm("mov.b64 {%0, %1}, %2;" : "=r"(l), "=r"(h) : "l"(a1));
            s1 = __uint_as_float(l) + __uint_as_float(h);
            asm("mov.b64 {%0, %1}, %2;" : "=r"(l), "=r"(h) : "l"(a2));
            s2 = __uint_as_float(l) + __uint_as_float(h);
            asm("mov.b64 {%0, %1}, %2;" : "=r"(l), "=r"(h) : "l"(a3));
            s3 = __uint_as_float(l) + __uint_as_float(h);
        }
        *(float4*)&red[ks][c][0] = make_float4(s0, s1, s2, s3);
        __syncthreads();

        // ---- epilogue: 256 threads, one value each ----
        {
            float v = xw + ((red[0][ec][eb] + red[1][ec][eb]) +
                            (red[2][ec][eb] + red[3][ec][eb]));
            v = fast_tanh(v);

            // Fire the value at all 7 peers' hbuf[q^1] immediately.
            const unsigned int hoff = (unsigned int)(q ^ 1) * 8192u;
            const unsigned int moff = (unsigned int)(q ^ 1) * 8u;
            const unsigned int vb   = __float_as_uint(v);
#pragma unroll
            for (int r = 0; r < 7; r++)
                asm volatile(
                    "st.async.shared::cluster.mbarrier::complete_tx::bytes.b32 "
                    "[%0], %1, [%2];"
                    :: "r"(ra[r] + hoff), "r"(vb), "r"(rm[r] + moff)
                    : "memory");

            // Local copy (plain smem store; ordered by the syncthreads below).
            *(float*)((char*)hbuf + (lslot - hb_base) + hoff) = v;

            hidden[gaddr] = v;               // overwrite xw[t] in place
            if (t == Ssz - 1)
                hlast[(size_t)(b0 + eb) * Hsz + egc] = v;
            else
                gaddr += Hsz;
        }
        __syncthreads();   // local hbuf[q^1] writes + red reuse protection
    }

    // Drain final inbound phase (t=2047 targets mb[0]); cluster-sync to exit.
    mbar_wait(mb_base, ph0);
    asm volatile("barrier.cluster.arrive.aligned;" ::: "memory");
    asm volatile("barrier.cluster.wait.aligned;" ::: "memory");
}

extern "C" void kernel_launch(void* const* d_in, const int* in_sizes, int n_in,
                              void* d_out, int out_size) {
    const float* x  = (const float*)d_in[0];   // [64,2048,512]
    const float* Wi = (const float*)d_in[1];   // [512,512]
    const float* Ui = (const float*)d_in[2];   // [512,512]
    const float* bi = (const float*)d_in[3];   // [512]

    float* hidden = (float*)d_out;                        // [B,S,H]
    float* hlast  = hidden + (size_t)Bsz * Ssz * Hsz;     // [B,H]

    dim3 g1(Hsz / 128, (Bsz * Ssz) / 128);   // (4, 1024)
    sgemm_xw<<<g1, 256>>>(x, Wi, bi, hidden);

    rnn_scan<<<128, 256>>>(Ui, hidden, hlast);
}

// round 9
// speedup vs baseline: 1.2957x; 1.2957x over previous
#include <cuda_runtime.h>
#include <cstdint>

#define Bsz 64
#define Ssz 2048
#define Isz 512
#define Hsz 512

// ============================================================
// Phase 1: xW = x @ W + b   (M=131072, K=512, N=512)
// 128x128 block tile, BK=8, 256 threads, 8x8 thread tile,
// packed f32x2 FMA. 2 CTAs/SM hides sync bubbles.
// ============================================================
__global__ __launch_bounds__(256, 2) void sgemm_xw(
    const float* __restrict__ A,
    const float* __restrict__ Wm,
    const float* __restrict__ bias,
    float* __restrict__ C)
{
    constexpr int K = 512, N = 512;
    __shared__ float As[8][128];
    __shared__ float Bs[8][128];

    const int tid  = threadIdx.x;
    const int bm   = blockIdx.y, bn = blockIdx.x;
    const int arow = tid >> 1, acol = (tid & 1) << 2;
    const int brow = tid >> 5, bcol = (tid & 31) << 2;
    const int tx   = tid & 15, ty = tid >> 4;

    const float* Ab = A + (size_t)bm * 128 * K;
    const float* Bb = Wm + bn * 128;

    unsigned long long acc[8][4];
#pragma unroll
    for (int i = 0; i < 8; i++)
#pragma unroll
        for (int j = 0; j < 4; j++) acc[i][j] = 0ull;

    for (int kk = 0; kk < K; kk += 8) {
        float4 av = *(const float4*)(Ab + (size_t)arow * K + kk + acol);
        float4 bv = *(const float4*)(Bb + (size_t)(kk + brow) * N + bcol);
        __syncthreads();
        As[acol + 0][arow] = av.x;
        As[acol + 1][arow] = av.y;
        As[acol + 2][arow] = av.z;
        As[acol + 3][arow] = av.w;
        *(float4*)&Bs[brow][bcol] = bv;
        __syncthreads();
#pragma unroll
        for (int k = 0; k < 8; k++) {
            float4 a0 = *(const float4*)&As[k][ty * 8];
            float4 a1 = *(const float4*)&As[k][ty * 8 + 4];
            ulonglong2 b0 = *(const ulonglong2*)&Bs[k][tx * 8];
            ulonglong2 b1 = *(const ulonglong2*)&Bs[k][tx * 8 + 4];
            float ar[8] = {a0.x, a0.y, a0.z, a0.w, a1.x, a1.y, a1.z, a1.w};
            unsigned long long br[4] = {b0.x, b0.y, b1.x, b1.y};
#pragma unroll
            for (int i = 0; i < 8; i++) {
                unsigned long long ad;
                unsigned int au = __float_as_uint(ar[i]);
                asm("mov.b64 %0, {%1, %1};" : "=l"(ad) : "r"(au));
#pragma unroll
                for (int j = 0; j < 4; j++)
                    asm("fma.rn.f32x2 %0, %1, %2, %0;"
                        : "+l"(acc[i][j]) : "l"(ad), "l"(br[j]));
            }
        }
    }

    const int cb = bn * 128 + tx * 8;
    ulonglong2 bb0 = *(const ulonglong2*)&bias[cb];
    ulonglong2 bb1 = *(const ulonglong2*)&bias[cb + 4];
    unsigned long long bz[4] = {bb0.x, bb0.y, bb1.x, bb1.y};
#pragma unroll
    for (int i = 0; i < 8; i++) {
        size_t row = (size_t)bm * 128 + ty * 8 + i;
        float* Crow = C + row * N + cb;
#pragma unroll
        for (int j = 0; j < 4; j++) {
            unsigned long long v;
            asm("add.rn.f32x2 %0, %1, %2;" : "=l"(v) : "l"(acc[i][j]), "l"(bz[j]));
            *(unsigned long long*)(Crow + 2 * j) = v;
        }
    }
}

// fast tanh: 1 - 2/(exp(2x)+1) via MUFU EX2 + RCP (abs err ~1e-7).
__device__ __forceinline__ float fast_tanh(float x) {
    float e;
    asm("ex2.approx.f32 %0, %1;" : "=f"(e) : "f"(x * 2.8853900817779268f));
    float r;
    asm("rcp.approx.f32 %0, %1;" : "=f"(r) : "f"(e + 1.0f));
    return fmaf(-2.0f, r, 1.0f);
}

__device__ __forceinline__ void mbar_wait(unsigned int addr, unsigned int parity) {
    unsigned int done;
    do {
        asm volatile(
            "{\n\t.reg .pred p;\n\t"
            "mbarrier.try_wait.parity.acquire.cta.shared::cta.b64 p, [%1], %2, 0x989680;\n\t"
            "selp.b32 %0, 1, 0, p;\n\t}"
            : "=r"(done) : "r"(addr), "r"(parity) : "memory");
    } while (!done);
}

// ============================================================
// Phase 2: persistent cluster RNN scan, per-quarter dependencies.
// 16 clusters x 8 CTAs, 256 threads/CTA. Cluster owns 4 batches;
// CTA rank r owns U columns [64r,64r+64) as pre-packed k-pairs in
// registers. k-quarter ks consumes ONLY the h-blocks of ranks
// {2ks, 2ks+1}, so each quarter has its own mbarrier: a warp-group
// starts its FMA as soon as ITS two inbound 1KB blocks land, while
// the other quarters' messages are still in flight.
// Exchange: 7 x 1KB cp.async.bulk smem->remote smem, complete_tx on
// the receiver's quarter barrier mb[rank>>1][buf].
// ============================================================
__global__ void __launch_bounds__(256, 1) __cluster_dims__(8, 1, 1)
rnn_scan(const float* __restrict__ U,      // [512,512] row-major [k][h]
         float* __restrict__ hidden,       // [B,S,H]: in = xW+b, out = h
         float* __restrict__ hlast)        // [B,H]
{
    __shared__ __align__(128) float hbuf[2][256][4][2];   // [buf][kp][b][kk] 16KB
    __shared__ __align__(16)  float red[4][64][4];        // [ks][col][b]
    __shared__ __align__(16)  unsigned long long mbar[4][2]; // [quarter][buf]

    const int tid = threadIdx.x;
    unsigned int rank;
    asm("mov.u32 %0, %%cluster_ctarank;" : "=r"(rank));
    const int cid = blockIdx.x >> 3;
    const int b0  = cid * 4;
    const int ks  = tid >> 6;              // 0..3 (k-quarter)
    const int c   = tid & 63;
    const int cg  = (int)rank * 64 + c;

    // Pre-pack U k-pairs: Upack[j] = (U[k0][cg], U[k0+1][cg]), k0 = ks*128+2j.
    unsigned long long Upack[64];
#pragma unroll
    for (int j = 0; j < 64; j++) {
        int k0 = ks * 128 + 2 * j;
        unsigned int lo = __float_as_uint(U[(size_t)k0 * Hsz + cg]);
        unsigned int hi = __float_as_uint(U[(size_t)(k0 + 1) * Hsz + cg]);
        asm("mov.b64 %0, {%1, %2};" : "=l"(Upack[j]) : "r"(lo), "r"(hi));
    }

    const unsigned int hb_base =
        (unsigned int)__cvta_generic_to_shared(&hbuf[0][0][0][0]);
    const unsigned int mb_base =
        (unsigned int)__cvta_generic_to_shared(&mbar[0][0]);

    // Quarter ks receives from ranks {2ks, 2ks+1}. Own block is written
    // locally (no tx), so expect only remote bytes.
    const unsigned int expq =
        ((int)(rank >> 1) == ks) ? 1024u : 2048u;
    // This CTA's quarter barrier (buffer 0 address; buffer 1 = +8).
    const unsigned int my_mb = mb_base + (unsigned int)ks * 16u;

    // Init: zero both h buffers; 8 mbarriers count=1; pre-arm buffer-1 set.
    {
        float* hz = &hbuf[0][0][0][0];
        for (int i = tid; i < 2 * 256 * 4 * 2; i += 256) hz[i] = 0.0f;
    }
    if (tid == 0) {
#pragma unroll
        for (int qq = 0; qq < 4; qq++) {
#pragma unroll
            for (int b = 0; b < 2; b++)
                asm volatile("mbarrier.init.shared.b64 [%0], %1;"
                             :: "r"(mb_base + qq * 16u + b * 8u), "r"(1u)
                             : "memory");
            const unsigned int e =
                ((int)(rank >> 1) == qq) ? 1024u : 2048u;
            asm volatile("mbarrier.arrive.expect_tx.shared.b64 _, [%0], %1;"
                         :: "r"(mb_base + qq * 16u + 8u), "r"(e) : "memory");
        }
    }
    __syncthreads();
    asm volatile("barrier.cluster.arrive.aligned;" ::: "memory");
    asm volatile("barrier.cluster.wait.aligned;" ::: "memory");

    // Epilogue thread state (tid < 64): column egc, 4 batches.
    const int egc = (int)rank * 64 + tid;
    size_t gaddr = 0;
    if (tid < 64)
        gaddr = ((size_t)b0 * Ssz) * Hsz + egc;

    unsigned int ph0 = 0, ph1 = 0;

    for (int t = 0; t < Ssz; t++) {
        const int q = t & 1;
        const unsigned int mbq = my_mb + (unsigned int)q * 8u;

        // xw prefetch (independent of the wait; issue early).
        float xw0 = 0.f, xw1 = 0.f, xw2 = 0.f, xw3 = 0.f;
        if (tid < 64) {
            xw0 = __ldg(hidden + gaddr);
            xw1 = __ldg(hidden + gaddr + (size_t)Ssz * Hsz);
            xw2 = __ldg(hidden + gaddr + 2 * (size_t)Ssz * Hsz);
            xw3 = __ldg(hidden + gaddr + 3 * (size_t)Ssz * Hsz);
        }

        // Wait only for OUR quarter's inbound blocks (buffer q).
        if (t > 0) {
            if (q == 0) { mbar_wait(mbq, ph0); ph0 ^= 1; }
            else        { mbar_wait(mbq, ph1); ph1 ^= 1; }
        }
        // Re-arm our quarter barrier for its next phase (consumed at t+2).
        if ((tid & 63) == 0)
            asm volatile("mbarrier.arrive.expect_tx.shared.b64 _, [%0], %1;"
                         :: "r"(mbq), "r"(expq) : "memory");

        // ---- partials: 4 batches x 1 col x 64 k-pairs (f32x2) ----
        const ulonglong2* hk = (const ulonglong2*)&hbuf[q][ks * 64][0][0];
        unsigned long long a0 = 0ull, a1 = 0ull, a2 = 0ull, a3 = 0ull;
#pragma unroll
        for (int j = 0; j < 64; j++) {
            ulonglong2 p01 = hk[2 * j];       // b0, b1 pairs
            ulonglong2 p23 = hk[2 * j + 1];   // b2, b3 pairs
            asm("fma.rn.f32x2 %0, %1, %2, %0;" : "+l"(a0) : "l"(Upack[j]), "l"(p01.x));
            asm("fma.rn.f32x2 %0, %1, %2, %0;" : "+l"(a1) : "l"(Upack[j]), "l"(p01.y));
            asm("fma.rn.f32x2 %0, %1, %2, %0;" : "+l"(a2) : "l"(Upack[j]), "l"(p23.x));
            asm("fma.rn.f32x2 %0, %1, %2, %0;" : "+l"(a3) : "l"(Upack[j]), "l"(p23.y));
        }
        float s0, s1, s2, s3;
        {
            unsigned int l, h;
            asm("mov.b64 {%0, %1}, %2;" : "=r"(l), "=r"(h) : "l"(a0));
            s0 = __uint_as_float(l) + __uint_as_float(h);
            asm("mov.b64 {%0, %1}, %2;" : "=r"(l), "=r"(h) : "l"(a1));
            s1 = __uint_as_float(l) + __uint_as_float(h);
            asm("mov.b64 {%0, %1}, %2;" : "=r"(l), "=r"(h) : "l"(a2));
            s2 = __uint_as_float(l) + __uint_as_float(h);
            asm("mov.b64 {%0, %1}, %2;" : "=r"(l), "=r"(h) : "l"(a3));
            s3 = __uint_as_float(l) + __uint_as_float(h);
        }
        *(float4*)&red[ks][c][0] = make_float4(s0, s1, s2, s3);
        __syncthreads();

        // ---- epilogue (tid < 64): finalize, write own h block locally ----
        if (tid < 64) {
            float4 r0 = *(const float4*)&red[0][tid][0];
            float4 r1 = *(const float4*)&red[1][tid][0];
            float4 r2 = *(const float4*)&red[2][tid][0];
            float4 r3 = *(const float4*)&red[3][tid][0];
            float v0 = fast_tanh(xw0 + (r0.x + r1.x) + (r2.x + r3.x));
            float v1 = fast_tanh(xw1 + (r0.y + r1.y) + (r2.y + r3.y));
            float v2 = fast_tanh(xw2 + (r0.z + r1.z) + (r2.z + r3.z));
            float v3 = fast_tanh(xw3 + (r0.w + r1.w) + (r2.w + r3.w));

            // local write into hbuf[q^1], k-pair layout
            float* lhb = &hbuf[q ^ 1][egc >> 1][0][egc & 1];
            lhb[0] = v0; lhb[2] = v1; lhb[4] = v2; lhb[6] = v3;

            hidden[gaddr]                         = v0;  // overwrite xw[t]
            hidden[gaddr + (size_t)Ssz * Hsz]     = v1;
            hidden[gaddr + 2 * (size_t)Ssz * Hsz] = v2;
            hidden[gaddr + 3 * (size_t)Ssz * Hsz] = v3;
            if (t == Ssz - 1) {
                const size_t lb = (size_t)b0 * Hsz + egc;
                hlast[lb]           = v0;
                hlast[lb + Hsz]     = v1;
                hlast[lb + 2 * Hsz] = v2;
                hlast[lb + 3 * Hsz] = v3;
            } else {
                gaddr += Hsz;
            }
        }
        __syncthreads();   // own block fully written before bulk reads it

        // ---- push own 1KB block to the 7 peers' hbuf[q^1], targeting the
        // receiver-side quarter barrier for OUR rank's k-range ----
        if (tid < 7) {
            asm volatile("fence.proxy.async.shared::cta;" ::: "memory");
            const unsigned int off =
                (unsigned int)(q ^ 1) * 8192u + rank * 1024u;
            const unsigned int src = hb_base + off;
            const unsigned int pr  = (rank + 1u + (unsigned int)tid) & 7u;
            const unsigned int mb_tgt =
                mb_base + (rank >> 1) * 16u + (unsigned int)(q ^ 1) * 8u;
            unsigned int dst, rmb;
            asm("mapa.shared::cluster.u32 %0, %1, %2;"
                : "=r"(dst) : "r"(src), "r"(pr));
            asm("mapa.shared::cluster.u32 %0, %1, %2;"
                : "=r"(rmb) : "r"(mb_tgt), "r"(pr));
            asm volatile(
                "cp.async.bulk.shared::cluster.shared::cta.mbarrier::complete_tx::bytes "
                "[%0], [%1], %2, [%3];"
                :: "r"(dst), "r"(src), "r"(1024u), "r"(rmb) : "memory");
        }
    }

    // Drain the final inbound phase (t=2047 targets buffer-0 barriers):
    // each warp-group waits its own quarter barrier, then cluster-sync.
    mbar_wait(my_mb, ph0);
    asm volatile("barrier.cluster.arrive.aligned;" ::: "memory");
    asm volatile("barrier.cluster.wait.aligned;" ::: "memory");
}

extern "C" void kernel_launch(void* const* d_in, const int* in_sizes, int n_in,
                              void* d_out, int out_size) {
    const float* x  = (const float*)d_in[0];   // [64,2048,512]
    const float* Wi = (const float*)d_in[1];   // [512,512]
    const float* Ui = (const float*)d_in[2];   // [512,512]
    const float* bi = (const float*)d_in[3];   // [512]

    float* hidden = (float*)d_out;                        // [B,S,H]
    float* hlast  = hidden + (size_t)Bsz * Ssz * Hsz;     // [B,H]

    dim3 g1(Hsz / 128, (Bsz * Ssz) / 128);   // (4, 1024)
    sgemm_xw<<<g1, 256>>>(x, Wi, bi, hidden);

    rnn_scan<<<128, 256>>>(Ui, hidden, hlast);
}

// round 10
// speedup vs baseline: 1.3441x; 1.0374x over previous
#include <cuda_runtime.h>
#include <cstdint>

#define Bsz 64
#define Ssz 2048
#define Isz 512
#define Hsz 512

// ============================================================
// Phase 1: xW = x @ W + b   (M=131072, K=512, N=512)
// 128x128 block tile, BK=8, 256 threads, 8x8 thread tile,
// packed f32x2 FMA. 2 CTAs/SM hides sync bubbles.
// ============================================================
__global__ __launch_bounds__(256, 2) void sgemm_xw(
    const float* __restrict__ A,
    const float* __restrict__ Wm,
    const float* __restrict__ bias,
    float* __restrict__ C)
{
    constexpr int K = 512, N = 512;
    __shared__ float As[8][128];
    __shared__ float Bs[8][128];

    const int tid  = threadIdx.x;
    const int bm   = blockIdx.y, bn = blockIdx.x;
    const int arow = tid >> 1, acol = (tid & 1) << 2;
    const int brow = tid >> 5, bcol = (tid & 31) << 2;
    const int tx   = tid & 15, ty = tid >> 4;

    const float* Ab = A + (size_t)bm * 128 * K;
    const float* Bb = Wm + bn * 128;

    unsigned long long acc[8][4];
#pragma unroll
    for (int i = 0; i < 8; i++)
#pragma unroll
        for (int j = 0; j < 4; j++) acc[i][j] = 0ull;

    for (int kk = 0; kk < K; kk += 8) {
        float4 av = *(const float4*)(Ab + (size_t)arow * K + kk + acol);
        float4 bv = *(const float4*)(Bb + (size_t)(kk + brow) * N + bcol);
        __syncthreads();
        As[acol + 0][arow] = av.x;
        As[acol + 1][arow] = av.y;
        As[acol + 2][arow] = av.z;
        As[acol + 3][arow] = av.w;
        *(float4*)&Bs[brow][bcol] = bv;
        __syncthreads();
#pragma unroll
        for (int k = 0; k < 8; k++) {
            float4 a0 = *(const float4*)&As[k][ty * 8];
            float4 a1 = *(const float4*)&As[k][ty * 8 + 4];
            ulonglong2 b0 = *(const ulonglong2*)&Bs[k][tx * 8];
            ulonglong2 b1 = *(const ulonglong2*)&Bs[k][tx * 8 + 4];
            float ar[8] = {a0.x, a0.y, a0.z, a0.w, a1.x, a1.y, a1.z, a1.w};
            unsigned long long br[4] = {b0.x, b0.y, b1.x, b1.y};
#pragma unroll
            for (int i = 0; i < 8; i++) {
                unsigned long long ad;
                unsigned int au = __float_as_uint(ar[i]);
                asm("mov.b64 %0, {%1, %1};" : "=l"(ad) : "r"(au));
#pragma unroll
                for (int j = 0; j < 4; j++)
                    asm("fma.rn.f32x2 %0, %1, %2, %0;"
                        : "+l"(acc[i][j]) : "l"(ad), "l"(br[j]));
            }
        }
    }

    const int cb = bn * 128 + tx * 8;
    ulonglong2 bb0 = *(const ulonglong2*)&bias[cb];
    ulonglong2 bb1 = *(const ulonglong2*)&bias[cb + 4];
    unsigned long long bz[4] = {bb0.x, bb0.y, bb1.x, bb1.y};
#pragma unroll
    for (int i = 0; i < 8; i++) {
        size_t row = (size_t)bm * 128 + ty * 8 + i;
        float* Crow = C + row * N + cb;
#pragma unroll
        for (int j = 0; j < 4; j++) {
            unsigned long long v;
            asm("add.rn.f32x2 %0, %1, %2;" : "=l"(v) : "l"(acc[i][j]), "l"(bz[j]));
            *(unsigned long long*)(Crow + 2 * j) = v;
        }
    }
}

// fast tanh: 1 - 2/(exp(2x)+1) via MUFU EX2 + RCP (abs err ~1e-7).
__device__ __forceinline__ float fast_tanh(float x) {
    float e;
    asm("ex2.approx.f32 %0, %1;" : "=f"(e) : "f"(x * 2.8853900817779268f));
    float r;
    asm("rcp.approx.f32 %0, %1;" : "=f"(r) : "f"(e + 1.0f));
    return fmaf(-2.0f, r, 1.0f);
}

__device__ __forceinline__ void mbar_wait(unsigned int addr, unsigned int parity) {
    unsigned int done;
    do {
        asm volatile(
            "{\n\t.reg .pred p;\n\t"
            "mbarrier.try_wait.parity.acquire.cta.shared::cta.b64 p, [%1], %2, 0x989680;\n\t"
            "selp.b32 %0, 1, 0, p;\n\t}"
            : "=r"(done) : "r"(addr), "r"(parity) : "memory");
    } while (!done);
}

// ============================================================
// Phase 2: persistent cluster RNN scan — 2 clusters per SM.
// 32 clusters x 8 CTAs (grid 256, occ 2), 256 threads/CTA,
// 2 batches per cluster. Two independent recurrences co-resident
// on each SM: while one cluster sits in its exchange tail, the
// other issues FMA. Per-quarter mbarriers (R9) + bulk-copy
// transport (R6): quarter ks consumes only ranks {2ks,2ks+1}'s
// 512B blocks and starts FMA the moment they land.
// ============================================================
__global__ void __launch_bounds__(256, 2) __cluster_dims__(8, 1, 1)
rnn_scan(const float* __restrict__ U,      // [512,512] row-major [k][h]
         float* __restrict__ hidden,       // [B,S,H]: in = xW+b, out = h
         float* __restrict__ hlast)        // [B,H]
{
    __shared__ __align__(128) float hbuf[2][256][2][2];   // [buf][kp][b][kk] 8KB
    __shared__ __align__(16)  float red[4][64][2];        // [ks][col][b] 2KB
    __shared__ __align__(16)  unsigned long long mbar[4][2]; // [quarter][buf]

    const int tid = threadIdx.x;
    unsigned int rank;
    asm("mov.u32 %0, %%cluster_ctarank;" : "=r"(rank));
    const int cid = blockIdx.x >> 3;       // cluster id 0..31
    const int b0  = cid * 2;               // 2 batches per cluster
    const int ks  = tid >> 6;              // 0..3 (k-quarter)
    const int c   = tid & 63;
    const int cg  = (int)rank * 64 + c;

    // Pre-pack U k-pairs: Upack[j] = (U[k0][cg], U[k0+1][cg]), k0 = ks*128+2j.
    unsigned long long Upack[64];
#pragma unroll
    for (int j = 0; j < 64; j++) {
        int k0 = ks * 128 + 2 * j;
        unsigned int lo = __float_as_uint(U[(size_t)k0 * Hsz + cg]);
        unsigned int hi = __float_as_uint(U[(size_t)(k0 + 1) * Hsz + cg]);
        asm("mov.b64 %0, {%1, %2};" : "=l"(Upack[j]) : "r"(lo), "r"(hi));
    }

    const unsigned int hb_base =
        (unsigned int)__cvta_generic_to_shared(&hbuf[0][0][0][0]);
    const unsigned int mb_base =
        (unsigned int)__cvta_generic_to_shared(&mbar[0][0]);

    // Quarter ks receives from ranks {2ks, 2ks+1} (512B each); own block
    // written locally (no tx).
    const unsigned int expq =
        ((int)(rank >> 1) == ks) ? 512u : 1024u;
    const unsigned int my_mb = mb_base + (unsigned int)ks * 16u;

    // Init: zero both h buffers; 8 mbarriers count=1; pre-arm buffer-1 set.
    {
        float* hz = &hbuf[0][0][0][0];
        for (int i = tid; i < 2 * 256 * 2 * 2; i += 256) hz[i] = 0.0f;
    }
    if (tid == 0) {
#pragma unroll
        for (int qq = 0; qq < 4; qq++) {
#pragma unroll
            for (int b = 0; b < 2; b++)
                asm volatile("mbarrier.init.shared.b64 [%0], %1;"
                             :: "r"(mb_base + qq * 16u + b * 8u), "r"(1u)
                             : "memory");
            const unsigned int e =
                ((int)(rank >> 1) == qq) ? 512u : 1024u;
            asm volatile("mbarrier.arrive.expect_tx.shared.b64 _, [%0], %1;"
                         :: "r"(mb_base + qq * 16u + 8u), "r"(e) : "memory");
        }
    }
    __syncthreads();
    asm volatile("barrier.cluster.arrive.aligned;" ::: "memory");
    asm volatile("barrier.cluster.wait.aligned;" ::: "memory");

    // Epilogue mapping (tid < 128): one (column, batch) value per thread.
    const int ec  = tid & 63;
    const int eb  = (tid >> 6) & 1;
    const int egc = (int)rank * 64 + ec;
    size_t gaddr = 0;
    if (tid < 128)
        gaddr = ((size_t)(b0 + eb) * Ssz) * Hsz + egc;

    unsigned int ph0 = 0, ph1 = 0;

    for (int t = 0; t < Ssz; t++) {
        const int q = t & 1;
        const unsigned int mbq = my_mb + (unsigned int)q * 8u;

        // xw prefetch (independent of the wait; issue early).
        float xw = 0.0f;
        if (tid < 128)
            xw = __ldg(hidden + gaddr);

        // Wait only for OUR quarter's inbound blocks (buffer q).
        if (t > 0) {
            if (q == 0) { mbar_wait(mbq, ph0); ph0 ^= 1; }
            else        { mbar_wait(mbq, ph1); ph1 ^= 1; }
        }
        // Re-arm our quarter barrier for its next phase (consumed at t+2).
        if ((tid & 63) == 0)
            asm volatile("mbarrier.arrive.expect_tx.shared.b64 _, [%0], %1;"
                         :: "r"(mbq), "r"(expq) : "memory");

        // ---- partials: 2 batches x 1 col x 64 k-pairs (f32x2) ----
        const ulonglong2* hk = (const ulonglong2*)&hbuf[q][ks * 64][0][0];
        unsigned long long a0 = 0ull, a1 = 0ull;
#pragma unroll
        for (int j = 0; j < 64; j++) {
            ulonglong2 p = hk[j];             // .x = batch0 k-pair, .y = batch1
            asm("fma.rn.f32x2 %0, %1, %2, %0;" : "+l"(a0) : "l"(Upack[j]), "l"(p.x));
            asm("fma.rn.f32x2 %0, %1, %2, %0;" : "+l"(a1) : "l"(Upack[j]), "l"(p.y));
        }
        float s0, s1;
        {
            unsigned int l, h;
            asm("mov.b64 {%0, %1}, %2;" : "=r"(l), "=r"(h) : "l"(a0));
            s0 = __uint_as_float(l) + __uint_as_float(h);
            asm("mov.b64 {%0, %1}, %2;" : "=r"(l), "=r"(h) : "l"(a1));
            s1 = __uint_as_float(l) + __uint_as_float(h);
        }
        *(float2*)&red[ks][c][0] = make_float2(s0, s1);
        __syncthreads();

        // ---- epilogue (tid < 128): one value each ----
        if (tid < 128) {
            float v = xw + ((red[0][ec][eb] + red[1][ec][eb]) +
                            (red[2][ec][eb] + red[3][ec][eb]));
            v = fast_tanh(v);

            // local write into hbuf[q^1], k-pair layout
            hbuf[q ^ 1][egc >> 1][eb][egc & 1] = v;

            hidden[gaddr] = v;               // overwrite xw[t] in place
            if (t == Ssz - 1)
                hlast[(size_t)(b0 + eb) * Hsz + egc] = v;
            else
                gaddr += Hsz;
        }
        __syncthreads();   // own block fully written before bulk reads it

        // ---- push own 512B block to the 7 peers' hbuf[q^1], targeting the
        // receiver-side quarter barrier for OUR rank's k-range ----
        if (tid < 7) {
            asm volatile("fence.proxy.async.shared::cta;" ::: "memory");
            const unsigned int off =
                (unsigned int)(q ^ 1) * 4096u + rank * 512u;
            const unsigned int src = hb_base + off;
            const unsigned int pr  = (rank + 1u + (unsigned int)tid) & 7u;
            const unsigned int mb_tgt =
                mb_base + (rank >> 1) * 16u + (unsigned int)(q ^ 1) * 8u;
            unsigned int dst, rmb;
            asm("mapa.shared::cluster.u32 %0, %1, %2;"
                : "=r"(dst) : "r"(src), "r"(pr));
            asm("mapa.shared::cluster.u32 %0, %1, %2;"
                : "=r"(rmb) : "r"(mb_tgt), "r"(pr));
            asm volatile(
                "cp.async.bulk.shared::cluster.shared::cta.mbarrier::complete_tx::bytes "
                "[%0], [%1], %2, [%3];"
                :: "r"(dst), "r"(src), "r"(512u), "r"(rmb) : "memory");
        }
    }

    // Drain the final inbound phase (t=2047 targets buffer-0 barriers):
    // each warp-group waits its own quarter barrier, then cluster-sync.
    mbar_wait(my_mb, ph0);
    asm volatile("barrier.cluster.arrive.aligned;" ::: "memory");
    asm volatile("barrier.cluster.wait.aligned;" ::: "memory");
}

extern "C" void kernel_launch(void* const* d_in, const int* in_sizes, int n_in,
                              void* d_out, int out_size) {
    const float* x  = (const float*)d_in[0];   // [64,2048,512]
    const float* Wi = (const float*)d_in[1];   // [512,512]
    const float* Ui = (const float*)d_in[2];   // [512,512]
    const float* bi = (const float*)d_in[3];   // [512]

    float* hidden = (float*)d_out;                        // [B,S,H]
    float* hlast  = hidden + (size_t)Bsz * Ssz * Hsz;     // [B,H]

    dim3 g1(Hsz / 128, (Bsz * Ssz) / 128);   // (4, 1024)
    sgemm_xw<<<g1, 256>>>(x, Wi, bi, hidden);

    // Phase 2: 32 clusters x 8 CTAs, 2 CTAs/SM (occupancy 2).
    rnn_scan<<<256, 256>>>(Ui, hidden, hlast);
}

// round 11
// speedup vs baseline: 1.7245x; 1.2829x over previous
#include <cuda_runtime.h>
#include <cstdint>

#define Bsz 64
#define Ssz 2048
#define Isz 512
#define Hsz 512

// ============================================================
// Phase 1: xW = x @ W + b   (M=131072, K=512, N=512)
// 128x128 block tile, BK=8, 256 threads, 8x8 thread tile,
// packed f32x2 FMA. 2 CTAs/SM hides sync bubbles.
// ============================================================
__global__ __launch_bounds__(256, 2) void sgemm_xw(
    const float* __restrict__ A,
    const float* __restrict__ Wm,
    const float* __restrict__ bias,
    float* __restrict__ C)
{
    constexpr int K = 512, N = 512;
    __shared__ float As[8][128];
    __shared__ float Bs[8][128];

    const int tid  = threadIdx.x;
    const int bm   = blockIdx.y, bn = blockIdx.x;
    const int arow = tid >> 1, acol = (tid & 1) << 2;
    const int brow = tid >> 5, bcol = (tid & 31) << 2;
    const int tx   = tid & 15, ty = tid >> 4;

    const float* Ab = A + (size_t)bm * 128 * K;
    const float* Bb = Wm + bn * 128;

    unsigned long long acc[8][4];
#pragma unroll
    for (int i = 0; i < 8; i++)
#pragma unroll
        for (int j = 0; j < 4; j++) acc[i][j] = 0ull;

    for (int kk = 0; kk < K; kk += 8) {
        float4 av = *(const float4*)(Ab + (size_t)arow * K + kk + acol);
        float4 bv = *(const float4*)(Bb + (size_t)(kk + brow) * N + bcol);
        __syncthreads();
        As[acol + 0][arow] = av.x;
        As[acol + 1][arow] = av.y;
        As[acol + 2][arow] = av.z;
        As[acol + 3][arow] = av.w;
        *(float4*)&Bs[brow][bcol] = bv;
        __syncthreads();
#pragma unroll
        for (int k = 0; k < 8; k++) {
            float4 a0 = *(const float4*)&As[k][ty * 8];
            float4 a1 = *(const float4*)&As[k][ty * 8 + 4];
            ulonglong2 b0 = *(const ulonglong2*)&Bs[k][tx * 8];
            ulonglong2 b1 = *(const ulonglong2*)&Bs[k][tx * 8 + 4];
            float ar[8] = {a0.x, a0.y, a0.z, a0.w, a1.x, a1.y, a1.z, a1.w};
            unsigned long long br[4] = {b0.x, b0.y, b1.x, b1.y};
#pragma unroll
            for (int i = 0; i < 8; i++) {
                unsigned long long ad;
                unsigned int au = __float_as_uint(ar[i]);
                asm("mov.b64 %0, {%1, %1};" : "=l"(ad) : "r"(au));
#pragma unroll
                for (int j = 0; j < 4; j++)
                    asm("fma.rn.f32x2 %0, %1, %2, %0;"
                        : "+l"(acc[i][j]) : "l"(ad), "l"(br[j]));
            }
        }
    }

    const int cb = bn * 128 + tx * 8;
    ulonglong2 bb0 = *(const ulonglong2*)&bias[cb];
    ulonglong2 bb1 = *(const ulonglong2*)&bias[cb + 4];
    unsigned long long bz[4] = {bb0.x, bb0.y, bb1.x, bb1.y};
#pragma unroll
    for (int i = 0; i < 8; i++) {
        size_t row = (size_t)bm * 128 + ty * 8 + i;
        float* Crow = C + row * N + cb;
#pragma unroll
        for (int j = 0; j < 4; j++) {
            unsigned long long v;
            asm("add.rn.f32x2 %0, %1, %2;" : "=l"(v) : "l"(acc[i][j]), "l"(bz[j]));
            *(unsigned long long*)(Crow + 2 * j) = v;
        }
    }
}

// fast tanh: 1 - 2/(exp(2x)+1) via MUFU EX2 + RCP (abs err ~1e-7).
__device__ __forceinline__ float fast_tanh(float x) {
    float e;
    asm("ex2.approx.f32 %0, %1;" : "=f"(e) : "f"(x * 2.8853900817779268f));
    float r;
    asm("rcp.approx.f32 %0, %1;" : "=f"(r) : "f"(e + 1.0f));
    return fmaf(-2.0f, r, 1.0f);
}

__device__ __forceinline__ void mbar_wait(unsigned int addr, unsigned int parity) {
    unsigned int done;
    do {
        asm volatile(
            "{\n\t.reg .pred p;\n\t"
            "mbarrier.try_wait.parity.acquire.cta.shared::cta.b64 p, [%1], %2, 0x989680;\n\t"
            "selp.b32 %0, 1, 0, p;\n\t}"
            : "=r"(done) : "r"(addr), "r"(parity) : "memory");
    } while (!done);
}

// Dynamic smem layout (bytes):
//   [0, 8192)        hbuf[2][256][2][2] floats
//   [8192, 10240)    red[4][64][2] floats
//   [10240, 10304)   mbar[4][2] u64
//   [10368, 75904)   Usm[32][256] u64  (k-pairs 32..63 of each thread)
#define HB_OFF   0u
#define RED_OFF  8192u
#define MB_OFF   10240u
#define USM_OFF  10368u
#define SMEM_TOTAL 75904

// ============================================================
// Phase 2: persistent cluster RNN scan — 2 clusters per SM,
// spill-free U (half registers, half shared memory).
// 32 clusters x 8 CTAs (grid 256, occ 2), 256 threads/CTA,
// 2 batches per cluster. Per-quarter mbarriers + bulk transport.
// ============================================================
__global__ void __launch_bounds__(256, 2) __cluster_dims__(8, 1, 1)
rnn_scan(const float* __restrict__ U,      // [512,512] row-major [k][h]
         float* __restrict__ hidden,       // [B,S,H]: in = xW+b, out = h
         float* __restrict__ hlast)        // [B,H]
{
    extern __shared__ __align__(128) char dsm[];

    const int tid = threadIdx.x;
    unsigned int rank;
    asm("mov.u32 %0, %%cluster_ctarank;" : "=r"(rank));
    const int cid = blockIdx.x >> 3;       // cluster id 0..31
    const int b0  = cid * 2;               // 2 batches per cluster
    const int ks  = tid >> 6;              // 0..3 (k-quarter)
    const int c   = tid & 63;
    const int cg  = (int)rank * 64 + c;

    unsigned long long* Usm = (unsigned long long*)(dsm + USM_OFF);

    // U k-pairs for this thread's quarter: j=0..31 in regs, 32..63 in smem.
    unsigned long long Upack[32];
#pragma unroll
    for (int j = 0; j < 32; j++) {
        int k0 = ks * 128 + 2 * j;
        unsigned int lo = __float_as_uint(U[(size_t)k0 * Hsz + cg]);
        unsigned int hi = __float_as_uint(U[(size_t)(k0 + 1) * Hsz + cg]);
        asm("mov.b64 %0, {%1, %2};" : "=l"(Upack[j]) : "r"(lo), "r"(hi));
    }
    for (int j = 32; j < 64; j++) {
        int k0 = ks * 128 + 2 * j;
        unsigned int lo = __float_as_uint(U[(size_t)k0 * Hsz + cg]);
        unsigned int hi = __float_as_uint(U[(size_t)(k0 + 1) * Hsz + cg]);
        unsigned long long u;
        asm("mov.b64 %0, {%1, %2};" : "=l"(u) : "r"(lo), "r"(hi));
        Usm[(j - 32) * 256 + tid] = u;
    }

    const unsigned int hb_base =
        (unsigned int)__cvta_generic_to_shared(dsm + HB_OFF);
    const unsigned int mb_base =
        (unsigned int)__cvta_generic_to_shared(dsm + MB_OFF);
    float* redp = (float*)(dsm + RED_OFF);

    // Quarter ks receives from ranks {2ks, 2ks+1} (512B each); own block
    // written locally (no tx).
    const unsigned int expq =
        ((int)(rank >> 1) == ks) ? 512u : 1024u;
    const unsigned int my_mb = mb_base + (unsigned int)ks * 16u;

    // Init: zero both h buffers; 8 mbarriers count=1; pre-arm buffer-1 set.
    {
        float* hz = (float*)(dsm + HB_OFF);
        for (int i = tid; i < 2048; i += 256) hz[i] = 0.0f;
    }
    if (tid == 0) {
#pragma unroll
        for (int qq = 0; qq < 4; qq++) {
#pragma unroll
            for (int b = 0; b < 2; b++)
                asm volatile("mbarrier.init.shared.b64 [%0], %1;"
                             :: "r"(mb_base + qq * 16u + b * 8u), "r"(1u)
                             : "memory");
            const unsigned int e =
                ((int)(rank >> 1) == qq) ? 512u : 1024u;
            asm volatile("mbarrier.arrive.expect_tx.shared.b64 _, [%0], %1;"
                         :: "r"(mb_base + qq * 16u + 8u), "r"(e) : "memory");
        }
    }
    __syncthreads();
    asm volatile("barrier.cluster.arrive.aligned;" ::: "memory");
    asm volatile("barrier.cluster.wait.aligned;" ::: "memory");

    // Epilogue mapping (tid < 128): one (column, batch) value per thread.
    const int ec  = tid & 63;
    const int eb  = (tid >> 6) & 1;
    const int egc = (int)rank * 64 + ec;
    size_t gaddr = 0;
    if (tid < 128)
        gaddr = ((size_t)(b0 + eb) * Ssz) * Hsz + egc;

    unsigned int ph0 = 0, ph1 = 0;

    for (int t = 0; t < Ssz; t++) {
        const int q = t & 1;
        const unsigned int mbq = my_mb + (unsigned int)q * 8u;

        // xw prefetch (independent of the wait; issue early).
        float xw = 0.0f;
        if (tid < 128)
            xw = __ldg(hidden + gaddr);

        // Wait only for OUR quarter's inbound blocks (buffer q).
        if (t > 0) {
            if (q == 0) { mbar_wait(mbq, ph0); ph0 ^= 1; }
            else        { mbar_wait(mbq, ph1); ph1 ^= 1; }
        }
        // Re-arm our quarter barrier for its next phase (consumed at t+2).
        if ((tid & 63) == 0)
            asm volatile("mbarrier.arrive.expect_tx.shared.b64 _, [%0], %1;"
                         :: "r"(mbq), "r"(expq) : "memory");

        // ---- partials: 2 batches x 1 col x 64 k-pairs (f32x2) ----
        const ulonglong2* hk =
            (const ulonglong2*)(dsm + HB_OFF + q * 4096 + ks * 1024);
        unsigned long long a0 = 0ull, a1 = 0ull;
#pragma unroll
        for (int j = 0; j < 32; j++) {
            ulonglong2 p = hk[j];             // .x = batch0 k-pair, .y = batch1
            asm("fma.rn.f32x2 %0, %1, %2, %0;" : "+l"(a0) : "l"(Upack[j]), "l"(p.x));
            asm("fma.rn.f32x2 %0, %1, %2, %0;" : "+l"(a1) : "l"(Upack[j]), "l"(p.y));
        }
#pragma unroll
        for (int j = 32; j < 64; j++) {
            unsigned long long u = Usm[(j - 32) * 256 + tid];
            ulonglong2 p = hk[j];
            asm("fma.rn.f32x2 %0, %1, %2, %0;" : "+l"(a0) : "l"(u), "l"(p.x));
            asm("fma.rn.f32x2 %0, %1, %2, %0;" : "+l"(a1) : "l"(u), "l"(p.y));
        }
        float s0, s1;
        {
            unsigned int l, h;
            asm("mov.b64 {%0, %1}, %2;" : "=r"(l), "=r"(h) : "l"(a0));
            s0 = __uint_as_float(l) + __uint_as_float(h);
            asm("mov.b64 {%0, %1}, %2;" : "=r"(l), "=r"(h) : "l"(a1));
            s1 = __uint_as_float(l) + __uint_as_float(h);
        }
        *(float2*)(redp + (ks * 64 + c) * 2) = make_float2(s0, s1);
        __syncthreads();

        // ---- epilogue (tid < 128): one value each ----
        if (tid < 128) {
            float v = xw + ((redp[(0 * 64 + ec) * 2 + eb] +
                             redp[(1 * 64 + ec) * 2 + eb]) +
                            (redp[(2 * 64 + ec) * 2 + eb] +
                             redp[(3 * 64 + ec) * 2 + eb]));
            v = fast_tanh(v);

            // local write into hbuf[q^1], k-pair layout
            *(float*)(dsm + HB_OFF + (q ^ 1) * 4096 +
                      (egc >> 1) * 16 + eb * 8 + (egc & 1) * 4) = v;

            hidden[gaddr] = v;               // overwrite xw[t] in place
            if (t == Ssz - 1)
                hlast[(size_t)(b0 + eb) * Hsz + egc] = v;
            else
                gaddr += Hsz;
        }
        __syncthreads();   // own block fully written before bulk reads it

        // ---- push own 512B block to the 7 peers' hbuf[q^1], targeting the
        // receiver-side quarter barrier for OUR rank's k-range ----
        if (tid < 7) {
            asm volatile("fence.proxy.async.shared::cta;" ::: "memory");
            const unsigned int off =
                (unsigned int)(q ^ 1) * 4096u + rank * 512u;
            const unsigned int src = hb_base + off;
            const unsigned int pr  = (rank + 1u + (unsigned int)tid) & 7u;
            const unsigned int mb_tgt =
                mb_base + (rank >> 1) * 16u + (unsigned int)(q ^ 1) * 8u;
            unsigned int dst, rmb;
            asm("mapa.shared::cluster.u32 %0, %1, %2;"
                : "=r"(dst) : "r"(src), "r"(pr));
            asm("mapa.shared::cluster.u32 %0, %1, %2;"
                : "=r"(rmb) : "r"(mb_tgt), "r"(pr));
            asm volatile(
                "cp.async.bulk.shared::cluster.shared::cta.mbarrier::complete_tx::bytes "
                "[%0], [%1], %2, [%3];"
                :: "r"(dst), "r"(src), "r"(512u), "r"(rmb) : "memory");
        }
    }

    // Drain the final inbound phase, then cluster-sync before exit.
    mbar_wait(my_mb, ph0);
    asm volatile("barrier.cluster.arrive.aligned;" ::: "memory");
    asm volatile("barrier.cluster.wait.aligned;" ::: "memory");
}

extern "C" void kernel_launch(void* const* d_in, const int* in_sizes, int n_in,
                              void* d_out, int out_size) {
    const float* x  = (const float*)d_in[0];   // [64,2048,512]
    const float* Wi = (const float*)d_in[1];   // [512,512]
    const float* Ui = (const float*)d_in[2];   // [512,512]
    const float* bi = (const float*)d_in[3];   // [512]

    float* hidden = (float*)d_out;                        // [B,S,H]
    float* hlast  = hidden + (size_t)Bsz * Ssz * Hsz;     // [B,H]

    dim3 g1(Hsz / 128, (Bsz * Ssz) / 128);   // (4, 1024)
    sgemm_xw<<<g1, 256>>>(x, Wi, bi, hidden);

    // Phase 2: 32 clusters x 8 CTAs, 2 CTAs/SM, 74.1 KB dyn smem each.
    cudaFuncSetAttribute(rnn_scan,
                         cudaFuncAttributeMaxDynamicSharedMemorySize,
                         SMEM_TOTAL);
    rnn_scan<<<256, 256, SMEM_TOTAL>>>(Ui, hidden, hlast);
}